// round 9
// baseline (speedup 1.0000x reference)
#include <cuda_runtime.h>

// out[p, i*16+j] = x[p, i] * W[i, j] + b[i, j]
//   p in [0, P=B*T), i in [0,128), j in [0,16)
// x: [P, 128] f32, W: [128,16] f32, b: [128,16] f32, out: [P, 2048] f32
//
// Chunk-per-thread: 512 threads; thread t owns float4 chunk t of each
// position (feature i = t>>2, quad q = t&3). Warp STG.128 = 512 B contiguous.
// Streaming stores (.cs): output is write-once.
//
// R8: persistent grid (4 CTAs/SM x 148 SMs = 592 blocks) with grid-stride
// loop over 8-position tiles. W/b register-preload happens once per block
// (was once per 4096 blocks = 67 MB of redundant L1/L2 reads), wave-tail
// quantization disappears, and next-tile loads pipeline above prior stores.
// regs pinned <=32 via __launch_bounds__(512,4) (R6 lesson: regs=40 loses a CTA).

#define C_IN   128
#define C_OUT  16
#define CHUNKS 512            // 2048 floats / 4 per position
#define TILE   8              // positions per tile
#define NBLOCKS 592           // 4 CTAs/SM * 148 SMs

__global__ __launch_bounds__(CHUNKS, 4) void realembed_kernel(
    const float* __restrict__ x,
    const float* __restrict__ W,
    const float* __restrict__ bias,
    float* __restrict__ out,
    int P)
{
    const int t = threadIdx.x;            // chunk index 0..511
    const int i = t >> 2;                 // feature 0..127
    const int q = t & 3;                  // quad within the 16 outputs

    // Load once per (persistent) block.
    const float4 w4 = *reinterpret_cast<const float4*>(W    + i * C_OUT + q * 4);
    const float4 b4 = *reinterpret_cast<const float4*>(bias + i * C_OUT + q * 4);

    const int numTiles = (P + TILE - 1) / TILE;

    const float* xp = x + (size_t)blockIdx.x * TILE * C_IN + i;
    float4*      op = reinterpret_cast<float4*>(out)
                      + (size_t)blockIdx.x * TILE * CHUNKS + t;
    const size_t xstep = (size_t)gridDim.x * TILE * C_IN;
    const size_t ostep = (size_t)gridDim.x * TILE * CHUNKS;

    for (int tile = blockIdx.x; tile < numTiles; tile += gridDim.x,
         xp += xstep, op += ostep) {
        const int pbase = tile * TILE;
        if (pbase + TILE <= P) {
            // Fast path: 8 independent LDGs in flight, then 8 store groups.
            float xv[TILE];
            #pragma unroll
            for (int k = 0; k < TILE; ++k)
                xv[k] = __ldg(xp + k * C_IN);

            #pragma unroll
            for (int k = 0; k < TILE; ++k) {
                float4 o;
                o.x = fmaf(xv[k], w4.x, b4.x);
                o.y = fmaf(xv[k], w4.y, b4.y);
                o.z = fmaf(xv[k], w4.z, b4.z);
                o.w = fmaf(xv[k], w4.w, b4.w);
                __stcs(op + k * CHUNKS, o);
            }
        } else {
            // Tail tile (not hit for P=32768).
            for (int k = 0; pbase + k < P && k < TILE; ++k) {
                float xv = __ldg(xp + k * C_IN);
                float4 o;
                o.x = fmaf(xv, w4.x, b4.x);
                o.y = fmaf(xv, w4.y, b4.y);
                o.z = fmaf(xv, w4.z, b4.z);
                o.w = fmaf(xv, w4.w, b4.w);
                __stcs(op + k * CHUNKS, o);
            }
        }
    }
}

extern "C" void kernel_launch(void* const* d_in, const int* in_sizes, int n_in,
                              void* d_out, int out_size)
{
    const float* x  = (const float*)d_in[0];   // [P, 128]
    const float* W  = (const float*)d_in[1];   // [128, 16]
    const float* b  = (const float*)d_in[2];   // [128, 16]
    float* out = (float*)d_out;                // [P, 2048]

    const int P = in_sizes[0] / C_IN;          // B*T = 32768

    int numTiles = (P + TILE - 1) / TILE;
    int blocks = NBLOCKS < numTiles ? NBLOCKS : numTiles;
    realembed_kernel<<<blocks, CHUNKS>>>(x, W, b, out, P);
}